// round 17
// baseline (speedup 1.0000x reference)
#include <cuda_runtime.h>
#include <cstdint>

// ============================================================================
// GENERICLayer (B=8192, D=64, H=128) via warp-level mma.sync (HMMA, bf16).
//   out = [z_q, -z_p] (exact fp32) + (z Wf^T)^2 * ((W2*silu'(z W1^T+b1)) @ W1)
// Exact collapse of the reference:
//   * eigh(diag(a^2)) reconstructs it exactly -> irr_d = a_d^2 * gS_d
//   * reversible = concat(z[:,32:], -z[:,:32])
//
// R16: occupancy push.  grid=256 x 32-row tiles, 8 warps = 2 row-slabs x
// 4-way n/h split (40 MMAs/warp), accumulators ~80 regs ->
// __launch_bounds__(256,2) => 2 CTAs/SM, 4 warps/SMSP, CTA pipelines overlap.
// Weight B-fragments prepacked once by a tiny prep kernel into __device__
// globals; co-resident CTAs share them through L1 (L1-hit after first touch).
//   phase 1: U (own 4 n-tiles, 32 h) + A (own 2 n-tiles), K=64  -> 24 MMAs
//   silu' in-register; own h-cols == own 2 phase-2 k-tiles (k = h)
//   phase 2: partial gS over own 2 k-tiles, all 8 n-tiles      -> 16 MMAs
//   4-way partial exchange in smem (32KB); each warp finalizes its 16 cols.
// ============================================================================

#define NBLK 256
#define THREADS 256

__device__ uint2 gBU[2048];   // [(kt*128 + h)*4 + q]  : B frags of W1^T (U GEMM)
__device__ uint2 gBF[1024];   // [(kt*64  + d)*4 + q]  : B frags of Wf^T (A GEMM)
__device__ uint2 gBG[2048];   // [(kt*64  + d)*4 + q]  : B frags of W1   (gS GEMM)

__device__ __forceinline__ unsigned packbf(float lo, float hi) {
    unsigned r;
    asm("cvt.rn.bf16x2.f32 %0, %1, %2;" : "=r"(r) : "f"(hi), "f"(lo));
    return r;
}
__device__ __forceinline__ void mma16816(float d[4], const unsigned a[4],
                                         unsigned b0, unsigned b1) {
    asm volatile(
        "mma.sync.aligned.m16n8k16.row.col.f32.bf16.bf16.f32 "
        "{%0,%1,%2,%3}, {%4,%5,%6,%7}, {%8,%9}, {%0,%1,%2,%3};"
        : "+f"(d[0]), "+f"(d[1]), "+f"(d[2]), "+f"(d[3])
        : "r"(a[0]), "r"(a[1]), "r"(a[2]), "r"(a[3]), "r"(b0), "r"(b1));
}

// ---- prep: pack weight fragments once (8 CTAs x 256 thr = 2048 threads) ----
__global__ void __launch_bounds__(256, 1)
prep_pack(const float* __restrict__ W1, const float* __restrict__ Wf)
{
    const int i = blockIdx.x * 256 + threadIdx.x;   // 0..2047
    {   // BU: pairs of W1 row h, cols kt*16 + {2q,2q+1,2q+8,2q+9}
        int h = (i >> 2) & 127, q = i & 3;
        int c = (i >> 9) * 16 + 2 * q;
        gBU[i] = make_uint2(packbf(W1[h * 64 + c],     W1[h * 64 + c + 1]),
                            packbf(W1[h * 64 + c + 8], W1[h * 64 + c + 9]));
    }
    if (i < 1024) {   // BF: pairs of Wf row d
        int d = (i >> 2) & 63, q = i & 3;
        int c = (i >> 8) * 16 + 2 * q;
        gBF[i] = make_uint2(packbf(Wf[d * 64 + c],     Wf[d * 64 + c + 1]),
                            packbf(Wf[d * 64 + c + 8], Wf[d * 64 + c + 9]));
    }
    {   // BG: pairs of W1 col d, rows kt*16 + {2q,2q+1,2q+8,2q+9}
        int d = (i >> 2) & 63, q = i & 3;
        int rr = (i >> 8) * 16 + 2 * q;
        gBG[i] = make_uint2(packbf(W1[rr * 64 + d],       W1[(rr + 1) * 64 + d]),
                            packbf(W1[(rr + 8) * 64 + d], W1[(rr + 9) * 64 + d]));
    }
}

// ---- main kernel -----------------------------------------------------------
__global__ void __launch_bounds__(THREADS, 2)
generic_layer_hmma(const float* __restrict__ z,
                   const float* __restrict__ b1,
                   const float* __restrict__ W2,
                   float* __restrict__ out)
{
    // XG[ws][src_q][ntile][lane] : 2*4*8*32 float4 = 32KB
    __shared__ float4 XG[2 * 4 * 8 * 32];

    const int tid = threadIdx.x;
    const int wid = tid >> 5, l = tid & 31;
    const int ws  = wid & 1;              // row-slab (0,1)
    const int q4  = wid >> 1;             // n/h quarter (0..3)
    const int lq  = l >> 2, lr = l & 3;
    const int row_base = blockIdx.x * 32;
    const int r0  = ws * 16 + lq;         // lane's base row in the 32-row tile

    // ---- A-fragments of Z straight from global (16 LDG.64 + pack) ---------
    const float* zr0p = z + (row_base + r0) * 64;
    const float* zr1p = z + (row_base + r0 + 8) * 64;
    unsigned afr[4][4];
    #pragma unroll
    for (int kt = 0; kt < 4; kt++) {
        int c = kt * 16 + 2 * lr;
        float2 a0 = *reinterpret_cast<const float2*>(zr0p + c);
        float2 a1 = *reinterpret_cast<const float2*>(zr1p + c);
        float2 a2 = *reinterpret_cast<const float2*>(zr0p + c + 8);
        float2 a3 = *reinterpret_cast<const float2*>(zr1p + c + 8);
        afr[kt][0] = packbf(a0.x, a0.y);
        afr[kt][1] = packbf(a1.x, a1.y);
        afr[kt][2] = packbf(a2.x, a2.y);
        afr[kt][3] = packbf(a3.x, a3.y);
    }

    // ---- phase 1: U (own 4 n-tiles) + A (own 2 n-tiles), K=64 -------------
    float uacc[4][4], facc[2][4];
    #pragma unroll
    for (int n = 0; n < 4; n++)
        #pragma unroll
        for (int j = 0; j < 4; j++) uacc[n][j] = 0.f;
    #pragma unroll
    for (int n = 0; n < 2; n++)
        #pragma unroll
        for (int j = 0; j < 4; j++) facc[n][j] = 0.f;

    #pragma unroll
    for (int kt = 0; kt < 4; kt++) {
        #pragma unroll
        for (int n = 0; n < 4; n++) {
            uint2 b = gBU[(kt * 128 + (q4 * 4 + n) * 8 + lq) * 4 + lr];
            mma16816(uacc[n], afr[kt], b.x, b.y);
        }
        #pragma unroll
        for (int n = 0; n < 2; n++) {
            uint2 b = gBF[(kt * 64 + (q4 * 2 + n) * 8 + lq) * 4 + lr];
            mma16816(facc[n], afr[kt], b.x, b.y);
        }
    }

    // ---- silu' in-register; C-frag pairs become A-frags for gS GEMM -------
    // own 32 h-cols = phase-2 k-tiles {2q4, 2q4+1}
    unsigned gfr[2][4];
    #pragma unroll
    for (int n = 0; n < 4; n++) {
        int c0 = (q4 * 4 + n) * 8 + lr * 2;
        float2 bb = *reinterpret_cast<const float2*>(b1 + c0);
        float2 ww = *reinterpret_cast<const float2*>(W2 + c0);
        float g[4];
        #pragma unroll
        for (int j = 0; j < 4; j++) {
            float u = uacc[n][j] + ((j & 1) ? bb.y : bb.x);
            float e = __expf(-u);
            float s = __fdividef(1.0f, 1.0f + e);
            g[j] = ((j & 1) ? ww.y : ww.x) * s * fmaf(u, 1.0f - s, 1.0f);
        }
        int jkt = n >> 1, hi = n & 1;
        gfr[jkt][hi * 2 + 0] = packbf(g[0], g[1]);   // rows r0
        gfr[jkt][hi * 2 + 1] = packbf(g[2], g[3]);   // rows r0+8
    }

    // ---- phase 2: partial gS over own 2 h k-tiles, all 8 n-tiles ----------
    float gsacc[8][4];
    #pragma unroll
    for (int n = 0; n < 8; n++)
        #pragma unroll
        for (int j = 0; j < 4; j++) gsacc[n][j] = 0.f;

    #pragma unroll
    for (int jkt = 0; jkt < 2; jkt++) {
        int ktg = q4 * 2 + jkt;
        #pragma unroll
        for (int n = 0; n < 8; n++) {
            uint2 b = gBG[(ktg * 64 + n * 8 + lq) * 4 + lr];
            mma16816(gsacc[n], gfr[jkt], b.x, b.y);
        }
    }

    // ---- exchange: publish partials for all 8 n-tiles under own src slot --
    #pragma unroll
    for (int n = 0; n < 8; n++) {
        const float* gp = gsacc[n];
        XG[((ws * 4 + q4) * 8 + n) * 32 + l] =
            make_float4(gp[0], gp[1], gp[2], gp[3]);
    }
    __syncthreads();

    // ---- epilogue: finalize own 2 n-tiles (own 16 output cols) ------------
    #pragma unroll
    for (int n2 = 0; n2 < 2; n2++) {
        int ng = q4 * 2 + n2;
        float gs0 = 0.f, gs1 = 0.f, gs2 = 0.f, gs3 = 0.f;
        #pragma unroll
        for (int sq = 0; sq < 4; sq++) {
            float4 px = XG[((ws * 4 + sq) * 8 + ng) * 32 + l];
            gs0 += px.x; gs1 += px.y; gs2 += px.z; gs3 += px.w;
        }
        int c0 = ng * 8 + lr * 2;
        int zc = c0 ^ 32;                       // rev source column (pair-safe)
        float sgn = (c0 < 32) ? 1.0f : -1.0f;
        float2 zv0 = *reinterpret_cast<const float2*>(zr0p + zc);   // L1 hit
        float2 zv1 = *reinterpret_cast<const float2*>(zr1p + zc);
        float a0 = facc[n2][0], a1 = facc[n2][1], a2 = facc[n2][2], a3 = facc[n2][3];
        float2 o0, o1;
        o0.x = fmaf(a0 * a0, gs0, sgn * zv0.x);
        o0.y = fmaf(a1 * a1, gs1, sgn * zv0.y);
        o1.x = fmaf(a2 * a2, gs2, sgn * zv1.x);
        o1.y = fmaf(a3 * a3, gs3, sgn * zv1.y);
        *reinterpret_cast<float2*>(out + (row_base + r0) * 64 + c0)     = o0;
        *reinterpret_cast<float2*>(out + (row_base + r0 + 8) * 64 + c0) = o1;
    }
}

extern "C" void kernel_launch(void* const* d_in, const int* in_sizes, int n_in,
                              void* d_out, int out_size) {
    const float* z  = (const float*)d_in[0];
    const float* W1 = (const float*)d_in[1];
    const float* b1 = (const float*)d_in[2];
    const float* W2 = (const float*)d_in[3];
    // d_in[4] = b2 : drops out of the gradient
    const float* Wf = (const float*)d_in[5];
    float* out = (float*)d_out;

    prep_pack<<<8, 256>>>(W1, Wf);
    generic_layer_hmma<<<NBLK, THREADS>>>(z, b1, W2, out);
}